// round 16
// baseline (speedup 1.0000x reference)
#include <cuda_runtime.h>
#include <cuda_fp16.h>
#include <math.h>
#include <cstdint>

#define N 1024
#define E 128
#define NEG 0.2f

#define I_PER_CTA 8
#define BMJ 128
#define LDH 136                   // half stride (272 B rows)
#define TILE_B (BMJ * LDH * 2)    // 34816
#define OFF_A0 0
#define OFF_A1 34816
#define OFF_B  69632
#define OFF_RS 104448             // rsum: 2 buffers x 128 x 2 floats
#define SMEM_DYN (OFF_RS + 2048)

// ---- scratch ----
__device__ float g_base[N * E];
__device__ float g_s[N];
__device__ float g_wa2[E];
__device__ float g_logits[(size_t)N * N];
__device__ __half g_Bh[E * E];   // pc_Wp fp16, [k][n]

__device__ __forceinline__ float lrelu(float x) { return fmaxf(x, NEG * x); }

__device__ __forceinline__ uint32_t smem_u32(const void* p) {
    return (uint32_t)__cvta_generic_to_shared(p);
}
__device__ __forceinline__ void ldsm_x4(uint32_t* r, uint32_t addr) {
    asm volatile("ldmatrix.sync.aligned.m8n8.x4.shared.b16 {%0,%1,%2,%3}, [%4];"
                 : "=r"(r[0]), "=r"(r[1]), "=r"(r[2]), "=r"(r[3]) : "r"(addr));
}
__device__ __forceinline__ void ldsm_x4_t(uint32_t* r, uint32_t addr) {
    asm volatile("ldmatrix.sync.aligned.m8n8.x4.trans.shared.b16 {%0,%1,%2,%3}, [%4];"
                 : "=r"(r[0]), "=r"(r[1]), "=r"(r[2]), "=r"(r[3]) : "r"(addr));
}
__device__ __forceinline__ void mma_h(uint32_t& d0, uint32_t& d1,
                                      const uint32_t* a, uint32_t b0, uint32_t b1) {
    asm volatile("mma.sync.aligned.m16n8k16.row.col.f16.f16.f16.f16 "
                 "{%0,%1},{%2,%3,%4,%5},{%6,%7},{%0,%1};"
                 : "+r"(d0), "+r"(d1)
                 : "r"(a[0]), "r"(a[1]), "r"(a[2]), "r"(a[3]), "r"(b0), "r"(b1));
}
__device__ __forceinline__ void mma_hf(float* d, const uint32_t* a, uint32_t b0, uint32_t b1) {
    asm volatile("mma.sync.aligned.m16n8k16.row.col.f32.f16.f16.f32 "
                 "{%0,%1,%2,%3},{%4,%5,%6,%7},{%8,%9},{%0,%1,%2,%3};"
                 : "+f"(d[0]), "+f"(d[1]), "+f"(d[2]), "+f"(d[3])
                 : "r"(a[0]), "r"(a[1]), "r"(a[2]), "r"(a[3]), "r"(b0), "r"(b1));
}
__device__ __forceinline__ uint32_t h2bits(__half2 v) { return *(uint32_t*)&v; }

// ---------------- fused k_pre: base+s per 8 rows, plus g_Bh row, plus wa2 (block 0) ----
#define IB 8
#define PRE_SMEM ((16384 + 2 * IB * 128 + 64 + 128) * 4)
__global__ void __launch_bounds__(128)
k_pre(const float* __restrict__ embs, const float* __restrict__ W,
      const float* __restrict__ pcW, const float* __restrict__ pcb,
      const float* __restrict__ aW) {
    extern __shared__ float ps[];
    float* Wsm = ps;
    float* es = ps + 16384;
    float* ws = es + IB * 128;
    float* scr = ws + IB * 128;        // 64
    float* a2sm = scr + 64;            // 128
    const int l = threadIdx.x;
    const int warp = l >> 5, lane = l & 31;
    const int i0 = blockIdx.x * IB;

    // fold of k_bh: convert one pc_Wp row to fp16
    g_Bh[blockIdx.x * 128 + l] = __float2half(pcW[E * E + blockIdx.x * 128 + l]);

#pragma unroll
    for (int t = 0; t < 32; t++)
        ((float4*)Wsm)[l + t * 128] = ((const float4*)W)[l + t * 128];
#pragma unroll
    for (int r = 0; r < IB; r++) es[r * 128 + l] = embs[(i0 + r) * 128 + l];
    __syncthreads();

    float acc[IB];
#pragma unroll
    for (int r = 0; r < IB; r++) acc[r] = 0.f;
    for (int k = 0; k < 128; k++) {
        float wv = Wsm[k * 128 + l];
#pragma unroll
        for (int r = 0; r < IB; r++) acc[r] = fmaf(es[r * 128 + k], wv, acc[r]);
    }
#pragma unroll
    for (int r = 0; r < IB; r++) ws[r * 128 + l] = acc[r];

    float a1 = aW[l];
#pragma unroll
    for (int r = 0; r < IB; r++) {
        float v = acc[r] * a1;
#pragma unroll
        for (int off = 16; off > 0; off >>= 1) v += __shfl_xor_sync(0xffffffffu, v, off);
        if (lane == 0) scr[r * 4 + warp] = v;
    }
    __syncthreads();
    if (l < IB)
        g_s[i0 + l] = scr[l * 4] + scr[l * 4 + 1] + scr[l * 4 + 2] + scr[l * 4 + 3];

    // fold of k_wa2: block 0 computes wa2 from smem-resident W (conflict-free rotation)
    if (blockIdx.x == 0) {
        a2sm[l] = aW[E + l];
        __syncthreads();
        float wv = 0.f;
#pragma unroll 8
        for (int k = 0; k < 128; k++) {
            int kk = (k + l) & 127;
            wv = fmaf(Wsm[l * 128 + kk], a2sm[kk], wv);
        }
        g_wa2[l] = wv;
    }
    __syncthreads();

#pragma unroll
    for (int t = 0; t < 32; t++)
        ((float4*)Wsm)[l + t * 128] = ((const float4*)pcW)[l + t * 128];
    __syncthreads();

    float b[IB];
    float bias = pcb[l];
#pragma unroll
    for (int r = 0; r < IB; r++) b[r] = bias;
    for (int k = 0; k < 128; k++) {
        float wv = Wsm[k * 128 + l];
#pragma unroll
        for (int r = 0; r < IB; r++) b[r] = fmaf(ws[r * 128 + k], wv, b[r]);
    }
#pragma unroll
    for (int r = 0; r < IB; r++) g_base[(size_t)(i0 + r) * 128 + l] = b[r];
}

// ---------------- big kernel: UNCHANGED from R15 ----------------
__global__ void __launch_bounds__(256, 2)
k_big(const float* __restrict__ pde, const int* __restrict__ adj,
      const float* __restrict__ ab_ptr) {
    extern __shared__ char sm[];
    const uint32_t sb = smem_u32(sm);

    const int tid = threadIdx.x;
    const int lane = tid & 31;
    const int wid = tid >> 5;
    const int grp = lane >> 2, tig = lane & 3;
    const int lrow = lane & 15, lcb = (lane >> 4) * 8;
    const int j0 = blockIdx.x * BMJ;
    const int i_base = blockIdx.y * I_PER_CTA;
    const float ab = ab_ptr[0];
    const __half2 slope = __float2half2_rn(NEG);

    const int wr = (wid & 3) * 32;
    const int wcg = wid >> 2;
    const int wc = wcg * 64;

#pragma unroll
    for (int t = 0; t < 8; t++) {
        int idx = tid + t * 256;
        int row = idx >> 4, c8 = (idx & 15) * 8;
        const float4* g = (const float4*)(g_base + (size_t)(j0 + row) * E + c8);
        float4 v0 = g[0], v1 = g[1];
        __half2 p0 = __floats2half2_rn(v0.x, v0.y);
        __half2 p1 = __floats2half2_rn(v0.z, v0.w);
        __half2 p2 = __floats2half2_rn(v1.x, v1.y);
        __half2 p3 = __floats2half2_rn(v1.z, v1.w);
        uint4 o;
        o.x = h2bits(p0); o.y = h2bits(p1); o.z = h2bits(p2); o.w = h2bits(p3);
        *(uint4*)(sm + OFF_A0 + (row * LDH + c8) * 2) = o;
    }
    __syncthreads();

    uint32_t bf0[2][8], bf1[2][8];
#pragma unroll
    for (int rb = 0; rb < 2; rb++)
#pragma unroll
        for (int q = 0; q < 4; q++) {
            uint32_t r[4];
            ldsm_x4(r, sb + OFF_A0 + ((wr + 16 * rb + lrow) * LDH + wc + 16 * q + lcb) * 2);
            bf0[rb][2 * q] = r[0]; bf1[rb][2 * q] = r[1];
            bf0[rb][2 * q + 1] = r[2]; bf1[rb][2 * q + 1] = r[3];
        }
    uint32_t w2lo[4], w2hi[4];
#pragma unroll
    for (int kb = 0; kb < 4; kb++) {
        if (grp == 0) {
            int k0 = wc + 16 * kb + 2 * tig;
            w2lo[kb] = h2bits(__floats2half2_rn(g_wa2[k0], g_wa2[k0 + 1]));
            w2hi[kb] = h2bits(__floats2half2_rn(g_wa2[k0 + 8], g_wa2[k0 + 9]));
        } else { w2lo[kb] = 0; w2hi[kb] = 0; }
    }
    __syncthreads();

#pragma unroll
    for (int t = 0; t < 8; t++) {
        int idx = tid + t * 256;
        int row = idx >> 4, c8 = (idx & 15) * 8;
        *(uint4*)(sm + OFF_B + (row * LDH + c8) * 2) = *(const uint4*)(g_Bh + row * E + c8);
    }
    {
        const float* gA = pde + ((size_t)i_base * N + j0) * E;
#pragma unroll
        for (int t = 0; t < 8; t++) {
            int idx = tid + t * 256;
            int row = idx >> 4, c8 = (idx & 15) * 8;
            const float4* g = (const float4*)(gA + (size_t)row * E + c8);
            float4 v0 = g[0], v1 = g[1];
            __half2 p0 = __floats2half2_rn(v0.x, v0.y);
            __half2 p1 = __floats2half2_rn(v0.z, v0.w);
            __half2 p2 = __floats2half2_rn(v1.x, v1.y);
            __half2 p3 = __floats2half2_rn(v1.z, v1.w);
            uint4 o;
            o.x = h2bits(p0); o.y = h2bits(p1); o.z = h2bits(p2); o.w = h2bits(p3);
            *(uint4*)(sm + OFF_A0 + (row * LDH + c8) * 2) = o;
        }
    }
    __syncthreads();

    const uint32_t bB = sb + OFF_B;

    for (int s = 0; s < I_PER_CTA; s++) {
        const uint32_t bA = sb + ((s & 1) ? OFF_A1 : OFF_A0);
        char* dst = sm + ((s & 1) ? OFF_A0 : OFF_A1);
        const int i = i_base + s;
        const bool do_copy = (s + 1 < I_PER_CTA);
        const float* gA = pde + ((size_t)(i_base + s + 1) * N + j0) * E;

        uint32_t fc0[2][8], fc1[2][8];
#pragma unroll
        for (int rb = 0; rb < 2; rb++)
#pragma unroll
            for (int cb = 0; cb < 8; cb++) { fc0[rb][cb] = 0; fc1[rb][cb] = 0; }

#pragma unroll
        for (int bq = 0; bq < 4; bq++) {
            float4 st[4];
            if (do_copy) {
#pragma unroll
                for (int u = 0; u < 2; u++) {
                    int t = bq * 2 + u;
                    int idx = tid + t * 256;
                    int row = idx >> 4, c8 = (idx & 15) * 8;
                    const float4* g = (const float4*)(gA + (size_t)row * E + c8);
                    st[2 * u] = g[0];
                    st[2 * u + 1] = g[1];
                }
            }
#pragma unroll
            for (int kk = 0; kk < 2; kk++) {
                const int ks = bq * 2 + kk;
                uint32_t a[2][4];
                ldsm_x4(a[0], bA + ((wr + lrow) * LDH + ks * 16 + lcb) * 2);
                ldsm_x4(a[1], bA + ((wr + 16 + lrow) * LDH + ks * 16 + lcb) * 2);
#pragma unroll
                for (int q = 0; q < 4; q++) {
                    uint32_t b[4];
                    ldsm_x4_t(b, bB + ((ks * 16 + lrow) * LDH + wc + 16 * q + lcb) * 2);
#pragma unroll
                    for (int rb = 0; rb < 2; rb++) {
                        mma_h(fc0[rb][2 * q], fc1[rb][2 * q], a[rb], b[0], b[1]);
                        mma_h(fc0[rb][2 * q + 1], fc1[rb][2 * q + 1], a[rb], b[2], b[3]);
                    }
                }
            }
            if (do_copy) {
#pragma unroll
                for (int u = 0; u < 2; u++) {
                    int t = bq * 2 + u;
                    int idx = tid + t * 256;
                    int row = idx >> 4, c8 = (idx & 15) * 8;
                    float4 v0 = st[2 * u], v1 = st[2 * u + 1];
                    __half2 p0 = __floats2half2_rn(v0.x, v0.y);
                    __half2 p1 = __floats2half2_rn(v0.z, v0.w);
                    __half2 p2 = __floats2half2_rn(v1.x, v1.y);
                    __half2 p3 = __floats2half2_rn(v1.z, v1.w);
                    uint4 o;
                    o.x = h2bits(p0); o.y = h2bits(p1); o.z = h2bits(p2); o.w = h2bits(p3);
                    *(uint4*)(dst + (row * LDH + c8) * 2) = o;
                }
            }
        }

#pragma unroll
        for (int rb = 0; rb < 2; rb++)
#pragma unroll
            for (int cb = 0; cb < 8; cb++) {
                __half2 v0 = __hadd2(*(__half2*)&fc0[rb][cb], *(__half2*)&bf0[rb][cb]);
                __half2 v1 = __hadd2(*(__half2*)&fc1[rb][cb], *(__half2*)&bf1[rb][cb]);
                *(__half2*)&fc0[rb][cb] = __hmax2(v0, __hmul2(v0, slope));
                *(__half2*)&fc1[rb][cb] = __hmax2(v1, __hmul2(v1, slope));
            }

        float* rsum = (float*)(sm + OFF_RS + (s & 1) * 1024);
        float racc[2][4];
#pragma unroll
        for (int rb = 0; rb < 2; rb++) {
#pragma unroll
            for (int e = 0; e < 4; e++) racc[rb][e] = 0.f;
#pragma unroll
            for (int kb = 0; kb < 4; kb++) {
                uint32_t aop[4] = { fc0[rb][2 * kb], fc1[rb][2 * kb],
                                    fc0[rb][2 * kb + 1], fc1[rb][2 * kb + 1] };
                mma_hf(racc[rb], aop, w2lo[kb], w2hi[kb]);
            }
            if (tig == 0) {
                rsum[(wr + 16 * rb + grp) * 2 + wcg] = racc[rb][0];
                rsum[(wr + 16 * rb + 8 + grp) * 2 + wcg] = racc[rb][2];
            }
        }
        __syncthreads();

        if (tid < 128) {
            float part = rsum[2 * tid] + rsum[2 * tid + 1];
            float lg = lrelu(g_s[i] + part + ab);
            size_t oidx = (size_t)i * N + j0 + tid;
            g_logits[oidx] = (adj[oidx] == 1) ? lg : -1e30f;
        }
    }
}

// ---------------- softmax + attn@embs + concat (float4 embs loads) ----------------
#define RPB 2
__global__ void __launch_bounds__(256)
k_out(const float* __restrict__ embs, float* __restrict__ out) {
    __shared__ float attn[RPB][N];          // 8 KB
    __shared__ float red16[16];
    __shared__ float4 psum[8][RPB][32];     // 8 KB
    const int i0 = blockIdx.x * RPB;
    const int t = threadIdx.x;
    const int warp = t >> 5, lane = t & 31;

    float inv[RPB];
#pragma unroll
    for (int r = 0; r < RPB; r++) {
        const float* lg = g_logits + (size_t)(i0 + r) * N;
        float v0 = lg[t], v1 = lg[t + 256], v2 = lg[t + 512], v3 = lg[t + 768];
        float m = fmaxf(fmaxf(v0, v1), fmaxf(v2, v3));
#pragma unroll
        for (int off = 16; off > 0; off >>= 1)
            m = fmaxf(m, __shfl_xor_sync(0xffffffffu, m, off));
        if (lane == 0) red16[warp] = m;
        __syncthreads();
        m = red16[0];
#pragma unroll
        for (int w = 1; w < 8; w++) m = fmaxf(m, red16[w]);

        float e0 = expf(v0 - m), e1 = expf(v1 - m), e2 = expf(v2 - m), e3 = expf(v3 - m);
        attn[r][t] = e0; attn[r][t + 256] = e1; attn[r][t + 512] = e2; attn[r][t + 768] = e3;
        float s = e0 + e1 + e2 + e3;
#pragma unroll
        for (int off = 16; off > 0; off >>= 1)
            s += __shfl_xor_sync(0xffffffffu, s, off);
        if (lane == 0) red16[8 + warp] = s;
        __syncthreads();
        s = red16[8];
#pragma unroll
        for (int w = 1; w < 8; w++) s += red16[8 + w];
        inv[r] = 1.f / s;
    }
    __syncthreads();

    // phase 2: each warp owns a 128-j slice; float4 over cols
    const float4* embs4 = (const float4*)embs;
    float4 acc[RPB];
#pragma unroll
    for (int r = 0; r < RPB; r++) acc[r] = make_float4(0.f, 0.f, 0.f, 0.f);
    const int jb = warp * 128;
#pragma unroll 4
    for (int j = jb; j < jb + 128; j++) {
        float4 ev = embs4[j * 32 + lane];
#pragma unroll
        for (int r = 0; r < RPB; r++) {
            float a = attn[r][j];
            acc[r].x = fmaf(a, ev.x, acc[r].x);
            acc[r].y = fmaf(a, ev.y, acc[r].y);
            acc[r].z = fmaf(a, ev.z, acc[r].z);
            acc[r].w = fmaf(a, ev.w, acc[r].w);
        }
    }
#pragma unroll
    for (int r = 0; r < RPB; r++) psum[warp][r][lane] = acc[r];
    __syncthreads();

    if (t < 64) {
        const int r = t >> 5;
        const int i = i0 + r;
        float4 s4 = psum[0][r][lane];
#pragma unroll
        for (int h = 1; h < 8; h++) {
            float4 p = psum[h][r][lane];
            s4.x += p.x; s4.y += p.y; s4.z += p.z; s4.w += p.w;
        }
        float iv = inv[r];
        s4.x *= iv; s4.y *= iv; s4.z *= iv; s4.w *= iv;
        ((float4*)out)[(size_t)i * 64 + 32 + lane] = s4;
        ((float4*)out)[(size_t)i * 64 + lane] = embs4[i * 32 + lane];
    }
}

// ---------------- launch ----------------
extern "C" void kernel_launch(void* const* d_in, const int* in_sizes, int n_in,
                              void* d_out, int out_size) {
    const float* embs = (const float*)d_in[0];
    const int*   adj  = (const int*)d_in[1];
    const float* pde  = (const float*)d_in[2];
    const float* W    = (const float*)d_in[3];
    const float* pcW  = (const float*)d_in[4];
    const float* pcb  = (const float*)d_in[5];
    const float* aW   = (const float*)d_in[6];
    const float* ab   = (const float*)d_in[7];
    float* out = (float*)d_out;

    cudaFuncSetAttribute(k_big, cudaFuncAttributeMaxDynamicSharedMemorySize,
                         (int)SMEM_DYN);
    cudaFuncSetAttribute(k_pre, cudaFuncAttributeMaxDynamicSharedMemorySize,
                         (int)PRE_SMEM);

    k_pre<<<N / IB, 128, PRE_SMEM>>>(embs, W, pcW, pcb, aW);      // launch 0
    k_big<<<dim3(N / BMJ, N / I_PER_CTA), 256, SMEM_DYN>>>(pde, adj, ab);  // launch 1
    k_out<<<N / RPB, 256>>>(embs, out);                           // launch 2
}

// round 17
// speedup vs baseline: 1.1681x; 1.1681x over previous
#include <cuda_runtime.h>
#include <cuda_fp16.h>
#include <math.h>
#include <cstdint>

#define N 1024
#define E 128
#define NEG 0.2f

#define I_PER_CTA 8
#define BMJ 128
#define LDH 136                   // half stride (272 B rows)
#define TILE_B (BMJ * LDH * 2)    // 34816
#define OFF_A0 0
#define OFF_A1 34816
#define OFF_B  69632
#define OFF_RS 104448             // rsum: 2 buffers x 128 x 2 floats
#define SMEM_DYN (OFF_RS + 2048)

// ---- scratch ----
__device__ float g_base[N * E];
__device__ float g_s[N];
__device__ float g_wa2[E];
__device__ float g_logits[(size_t)N * N];
__device__ __half g_Bh[E * E];   // pc_Wp fp16, [k][n]

__device__ __forceinline__ float lrelu(float x) { return fmaxf(x, NEG * x); }

__device__ __forceinline__ uint32_t smem_u32(const void* p) {
    return (uint32_t)__cvta_generic_to_shared(p);
}
__device__ __forceinline__ void ldsm_x4(uint32_t* r, uint32_t addr) {
    asm volatile("ldmatrix.sync.aligned.m8n8.x4.shared.b16 {%0,%1,%2,%3}, [%4];"
                 : "=r"(r[0]), "=r"(r[1]), "=r"(r[2]), "=r"(r[3]) : "r"(addr));
}
__device__ __forceinline__ void ldsm_x4_t(uint32_t* r, uint32_t addr) {
    asm volatile("ldmatrix.sync.aligned.m8n8.x4.trans.shared.b16 {%0,%1,%2,%3}, [%4];"
                 : "=r"(r[0]), "=r"(r[1]), "=r"(r[2]), "=r"(r[3]) : "r"(addr));
}
__device__ __forceinline__ void mma_h(uint32_t& d0, uint32_t& d1,
                                      const uint32_t* a, uint32_t b0, uint32_t b1) {
    asm volatile("mma.sync.aligned.m16n8k16.row.col.f16.f16.f16.f16 "
                 "{%0,%1},{%2,%3,%4,%5},{%6,%7},{%0,%1};"
                 : "+r"(d0), "+r"(d1)
                 : "r"(a[0]), "r"(a[1]), "r"(a[2]), "r"(a[3]), "r"(b0), "r"(b1));
}
__device__ __forceinline__ void mma_hf(float* d, const uint32_t* a, uint32_t b0, uint32_t b1) {
    asm volatile("mma.sync.aligned.m16n8k16.row.col.f32.f16.f16.f32 "
                 "{%0,%1,%2,%3},{%4,%5,%6,%7},{%8,%9},{%0,%1,%2,%3};"
                 : "+f"(d[0]), "+f"(d[1]), "+f"(d[2]), "+f"(d[3])
                 : "r"(a[0]), "r"(a[1]), "r"(a[2]), "r"(a[3]), "r"(b0), "r"(b1));
}
__device__ __forceinline__ uint32_t h2bits(__half2 v) { return *(uint32_t*)&v; }

// ---------------- fused k_pre: both weights staged at once, single load->sync ----------
#define IB 8
#define PRE_SMEM ((2 * 16384 + 2 * IB * 128 + 64 + 128) * 4)
__global__ void __launch_bounds__(128)
k_pre(const float* __restrict__ embs, const float* __restrict__ W,
      const float* __restrict__ pcW, const float* __restrict__ pcb,
      const float* __restrict__ aW) {
    extern __shared__ float ps[];
    float* Wsm = ps;                   // 16384
    float* Psm = ps + 16384;           // 16384 (pc_Wc)
    float* es = Psm + 16384;           // IB*128
    float* ws = es + IB * 128;         // IB*128
    float* scr = ws + IB * 128;        // 64
    float* a2sm = scr + 64;            // 128
    const int l = threadIdx.x;
    const int warp = l >> 5, lane = l & 31;
    const int i0 = blockIdx.x * IB;

    // fold of k_bh: convert one pc_Wp row to fp16 (independent of everything below)
    g_Bh[blockIdx.x * 128 + l] = __float2half(pcW[E * E + blockIdx.x * 128 + l]);

    // one combined load burst: W, pcW, es, a2 — then ONE sync
#pragma unroll
    for (int t = 0; t < 32; t++)
        ((float4*)Wsm)[l + t * 128] = ((const float4*)W)[l + t * 128];
#pragma unroll
    for (int t = 0; t < 32; t++)
        ((float4*)Psm)[l + t * 128] = ((const float4*)pcW)[l + t * 128];
#pragma unroll
    for (int r = 0; r < IB; r++) es[r * 128 + l] = embs[(i0 + r) * 128 + l];
    a2sm[l] = aW[E + l];
    __syncthreads();

    // gemm1: wf[r][l]
    float acc[IB];
#pragma unroll
    for (int r = 0; r < IB; r++) acc[r] = 0.f;
    for (int k = 0; k < 128; k++) {
        float wv = Wsm[k * 128 + l];
#pragma unroll
        for (int r = 0; r < IB; r++) acc[r] = fmaf(es[r * 128 + k], wv, acc[r]);
    }
#pragma unroll
    for (int r = 0; r < IB; r++) ws[r * 128 + l] = acc[r];

    // s reduction
    float a1 = aW[l];
#pragma unroll
    for (int r = 0; r < IB; r++) {
        float v = acc[r] * a1;
#pragma unroll
        for (int off = 16; off > 0; off >>= 1) v += __shfl_xor_sync(0xffffffffu, v, off);
        if (lane == 0) scr[r * 4 + warp] = v;
    }
    __syncthreads();
    if (l < IB)
        g_s[i0 + l] = scr[l * 4] + scr[l * 4 + 1] + scr[l * 4 + 2] + scr[l * 4 + 3];

    // fold of k_wa2 (block 0): conflict-free rotated read of row-major W
    if (blockIdx.x == 0) {
        float wv = 0.f;
#pragma unroll 8
        for (int k = 0; k < 128; k++) {
            int kk = (k + l) & 127;
            wv = fmaf(Wsm[l * 128 + kk], a2sm[kk], wv);
        }
        g_wa2[l] = wv;
    }

    // gemm2: base[r][l] (Psm already resident; ws written by this thread's own
    // column plus others' — ws[r][k] for all k needed; ws stores complete after
    // the scr sync above)
    float b[IB];
    float bias = pcb[l];
#pragma unroll
    for (int r = 0; r < IB; r++) b[r] = bias;
    for (int k = 0; k < 128; k++) {
        float wv = Psm[k * 128 + l];
#pragma unroll
        for (int r = 0; r < IB; r++) b[r] = fmaf(ws[r * 128 + k], wv, b[r]);
    }
#pragma unroll
    for (int r = 0; r < IB; r++) g_base[(size_t)(i0 + r) * 128 + l] = b[r];
}

// ---------------- big kernel: UNCHANGED (the 147us version) ----------------
__global__ void __launch_bounds__(256, 2)
k_big(const float* __restrict__ pde, const int* __restrict__ adj,
      const float* __restrict__ ab_ptr) {
    extern __shared__ char sm[];
    const uint32_t sb = smem_u32(sm);

    const int tid = threadIdx.x;
    const int lane = tid & 31;
    const int wid = tid >> 5;
    const int grp = lane >> 2, tig = lane & 3;
    const int lrow = lane & 15, lcb = (lane >> 4) * 8;
    const int j0 = blockIdx.x * BMJ;
    const int i_base = blockIdx.y * I_PER_CTA;
    const float ab = ab_ptr[0];
    const __half2 slope = __float2half2_rn(NEG);

    const int wr = (wid & 3) * 32;
    const int wcg = wid >> 2;
    const int wc = wcg * 64;

#pragma unroll
    for (int t = 0; t < 8; t++) {
        int idx = tid + t * 256;
        int row = idx >> 4, c8 = (idx & 15) * 8;
        const float4* g = (const float4*)(g_base + (size_t)(j0 + row) * E + c8);
        float4 v0 = g[0], v1 = g[1];
        __half2 p0 = __floats2half2_rn(v0.x, v0.y);
        __half2 p1 = __floats2half2_rn(v0.z, v0.w);
        __half2 p2 = __floats2half2_rn(v1.x, v1.y);
        __half2 p3 = __floats2half2_rn(v1.z, v1.w);
        uint4 o;
        o.x = h2bits(p0); o.y = h2bits(p1); o.z = h2bits(p2); o.w = h2bits(p3);
        *(uint4*)(sm + OFF_A0 + (row * LDH + c8) * 2) = o;
    }
    __syncthreads();

    uint32_t bf0[2][8], bf1[2][8];
#pragma unroll
    for (int rb = 0; rb < 2; rb++)
#pragma unroll
        for (int q = 0; q < 4; q++) {
            uint32_t r[4];
            ldsm_x4(r, sb + OFF_A0 + ((wr + 16 * rb + lrow) * LDH + wc + 16 * q + lcb) * 2);
            bf0[rb][2 * q] = r[0]; bf1[rb][2 * q] = r[1];
            bf0[rb][2 * q + 1] = r[2]; bf1[rb][2 * q + 1] = r[3];
        }
    uint32_t w2lo[4], w2hi[4];
#pragma unroll
    for (int kb = 0; kb < 4; kb++) {
        if (grp == 0) {
            int k0 = wc + 16 * kb + 2 * tig;
            w2lo[kb] = h2bits(__floats2half2_rn(g_wa2[k0], g_wa2[k0 + 1]));
            w2hi[kb] = h2bits(__floats2half2_rn(g_wa2[k0 + 8], g_wa2[k0 + 9]));
        } else { w2lo[kb] = 0; w2hi[kb] = 0; }
    }
    __syncthreads();

#pragma unroll
    for (int t = 0; t < 8; t++) {
        int idx = tid + t * 256;
        int row = idx >> 4, c8 = (idx & 15) * 8;
        *(uint4*)(sm + OFF_B + (row * LDH + c8) * 2) = *(const uint4*)(g_Bh + row * E + c8);
    }
    {
        const float* gA = pde + ((size_t)i_base * N + j0) * E;
#pragma unroll
        for (int t = 0; t < 8; t++) {
            int idx = tid + t * 256;
            int row = idx >> 4, c8 = (idx & 15) * 8;
            const float4* g = (const float4*)(gA + (size_t)row * E + c8);
            float4 v0 = g[0], v1 = g[1];
            __half2 p0 = __floats2half2_rn(v0.x, v0.y);
            __half2 p1 = __floats2half2_rn(v0.z, v0.w);
            __half2 p2 = __floats2half2_rn(v1.x, v1.y);
            __half2 p3 = __floats2half2_rn(v1.z, v1.w);
            uint4 o;
            o.x = h2bits(p0); o.y = h2bits(p1); o.z = h2bits(p2); o.w = h2bits(p3);
            *(uint4*)(sm + OFF_A0 + (row * LDH + c8) * 2) = o;
        }
    }
    __syncthreads();

    const uint32_t bB = sb + OFF_B;

    for (int s = 0; s < I_PER_CTA; s++) {
        const uint32_t bA = sb + ((s & 1) ? OFF_A1 : OFF_A0);
        char* dst = sm + ((s & 1) ? OFF_A0 : OFF_A1);
        const int i = i_base + s;
        const bool do_copy = (s + 1 < I_PER_CTA);
        const float* gA = pde + ((size_t)(i_base + s + 1) * N + j0) * E;

        uint32_t fc0[2][8], fc1[2][8];
#pragma unroll
        for (int rb = 0; rb < 2; rb++)
#pragma unroll
            for (int cb = 0; cb < 8; cb++) { fc0[rb][cb] = 0; fc1[rb][cb] = 0; }

#pragma unroll
        for (int bq = 0; bq < 4; bq++) {
            float4 st[4];
            if (do_copy) {
#pragma unroll
                for (int u = 0; u < 2; u++) {
                    int t = bq * 2 + u;
                    int idx = tid + t * 256;
                    int row = idx >> 4, c8 = (idx & 15) * 8;
                    const float4* g = (const float4*)(gA + (size_t)row * E + c8);
                    st[2 * u] = g[0];
                    st[2 * u + 1] = g[1];
                }
            }
#pragma unroll
            for (int kk = 0; kk < 2; kk++) {
                const int ks = bq * 2 + kk;
                uint32_t a[2][4];
                ldsm_x4(a[0], bA + ((wr + lrow) * LDH + ks * 16 + lcb) * 2);
                ldsm_x4(a[1], bA + ((wr + 16 + lrow) * LDH + ks * 16 + lcb) * 2);
#pragma unroll
                for (int q = 0; q < 4; q++) {
                    uint32_t b[4];
                    ldsm_x4_t(b, bB + ((ks * 16 + lrow) * LDH + wc + 16 * q + lcb) * 2);
#pragma unroll
                    for (int rb = 0; rb < 2; rb++) {
                        mma_h(fc0[rb][2 * q], fc1[rb][2 * q], a[rb], b[0], b[1]);
                        mma_h(fc0[rb][2 * q + 1], fc1[rb][2 * q + 1], a[rb], b[2], b[3]);
                    }
                }
            }
            if (do_copy) {
#pragma unroll
                for (int u = 0; u < 2; u++) {
                    int t = bq * 2 + u;
                    int idx = tid + t * 256;
                    int row = idx >> 4, c8 = (idx & 15) * 8;
                    float4 v0 = st[2 * u], v1 = st[2 * u + 1];
                    __half2 p0 = __floats2half2_rn(v0.x, v0.y);
                    __half2 p1 = __floats2half2_rn(v0.z, v0.w);
                    __half2 p2 = __floats2half2_rn(v1.x, v1.y);
                    __half2 p3 = __floats2half2_rn(v1.z, v1.w);
                    uint4 o;
                    o.x = h2bits(p0); o.y = h2bits(p1); o.z = h2bits(p2); o.w = h2bits(p3);
                    *(uint4*)(dst + (row * LDH + c8) * 2) = o;
                }
            }
        }

#pragma unroll
        for (int rb = 0; rb < 2; rb++)
#pragma unroll
            for (int cb = 0; cb < 8; cb++) {
                __half2 v0 = __hadd2(*(__half2*)&fc0[rb][cb], *(__half2*)&bf0[rb][cb]);
                __half2 v1 = __hadd2(*(__half2*)&fc1[rb][cb], *(__half2*)&bf1[rb][cb]);
                *(__half2*)&fc0[rb][cb] = __hmax2(v0, __hmul2(v0, slope));
                *(__half2*)&fc1[rb][cb] = __hmax2(v1, __hmul2(v1, slope));
            }

        float* rsum = (float*)(sm + OFF_RS + (s & 1) * 1024);
        float racc[2][4];
#pragma unroll
        for (int rb = 0; rb < 2; rb++) {
#pragma unroll
            for (int e = 0; e < 4; e++) racc[rb][e] = 0.f;
#pragma unroll
            for (int kb = 0; kb < 4; kb++) {
                uint32_t aop[4] = { fc0[rb][2 * kb], fc1[rb][2 * kb],
                                    fc0[rb][2 * kb + 1], fc1[rb][2 * kb + 1] };
                mma_hf(racc[rb], aop, w2lo[kb], w2hi[kb]);
            }
            if (tig == 0) {
                rsum[(wr + 16 * rb + grp) * 2 + wcg] = racc[rb][0];
                rsum[(wr + 16 * rb + 8 + grp) * 2 + wcg] = racc[rb][2];
            }
        }
        __syncthreads();

        if (tid < 128) {
            float part = rsum[2 * tid] + rsum[2 * tid + 1];
            float lg = lrelu(g_s[i] + part + ab);
            size_t oidx = (size_t)i * N + j0 + tid;
            g_logits[oidx] = (adj[oidx] == 1) ? lg : -1e30f;
        }
    }
}

// ---------------- softmax + attn@embs + concat: R15 version (measured good) ----------
#define RPB 2
__global__ void __launch_bounds__(256)
k_out(const float* __restrict__ embs, float* __restrict__ out) {
    __shared__ float attn[RPB][N];
    __shared__ float red16[16];
    __shared__ float partial[RPB][E];
    const int i0 = blockIdx.x * RPB;
    const int t = threadIdx.x;
    const int warp = t >> 5, lane = t & 31;

    float inv[RPB];
#pragma unroll
    for (int r = 0; r < RPB; r++) {
        const float* lg = g_logits + (size_t)(i0 + r) * N;
        float v0 = lg[t], v1 = lg[t + 256], v2 = lg[t + 512], v3 = lg[t + 768];
        float m = fmaxf(fmaxf(v0, v1), fmaxf(v2, v3));
#pragma unroll
        for (int off = 16; off > 0; off >>= 1)
            m = fmaxf(m, __shfl_xor_sync(0xffffffffu, m, off));
        if (lane == 0) red16[warp] = m;
        __syncthreads();
        m = red16[0];
#pragma unroll
        for (int w = 1; w < 8; w++) m = fmaxf(m, red16[w]);

        float e0 = expf(v0 - m), e1 = expf(v1 - m), e2 = expf(v2 - m), e3 = expf(v3 - m);
        attn[r][t] = e0; attn[r][t + 256] = e1; attn[r][t + 512] = e2; attn[r][t + 768] = e3;
        float s = e0 + e1 + e2 + e3;
#pragma unroll
        for (int off = 16; off > 0; off >>= 1)
            s += __shfl_xor_sync(0xffffffffu, s, off);
        if (lane == 0) red16[8 + warp] = s;
        __syncthreads();
        s = red16[8];
#pragma unroll
        for (int w = 1; w < 8; w++) s += red16[8 + w];
        inv[r] = 1.f / s;
    }
    __syncthreads();

    const int col = t & 127, h = t >> 7;
    float acc[RPB];
#pragma unroll
    for (int r = 0; r < RPB; r++) acc[r] = 0.f;
    const int jb = h * 512;
#pragma unroll 8
    for (int j = jb; j < jb + 512; j++) {
        float ev = embs[j * E + col];
#pragma unroll
        for (int r = 0; r < RPB; r++) acc[r] = fmaf(attn[r][j], ev, acc[r]);
    }
    if (h == 1) {
#pragma unroll
        for (int r = 0; r < RPB; r++) partial[r][col] = acc[r];
    }
    __syncthreads();
    if (h == 0) {
#pragma unroll
        for (int r = 0; r < RPB; r++) {
            int i = i0 + r;
            out[(size_t)i * (2 * E) + col] = embs[i * E + col];
            out[(size_t)i * (2 * E) + E + col] = (acc[r] + partial[r][col]) * inv[r];
        }
    }
}

// ---------------- launch ----------------
extern "C" void kernel_launch(void* const* d_in, const int* in_sizes, int n_in,
                              void* d_out, int out_size) {
    const float* embs = (const float*)d_in[0];
    const int*   adj  = (const int*)d_in[1];
    const float* pde  = (const float*)d_in[2];
    const float* W    = (const float*)d_in[3];
    const float* pcW  = (const float*)d_in[4];
    const float* pcb  = (const float*)d_in[5];
    const float* aW   = (const float*)d_in[6];
    const float* ab   = (const float*)d_in[7];
    float* out = (float*)d_out;

    cudaFuncSetAttribute(k_big, cudaFuncAttributeMaxDynamicSharedMemorySize,
                         (int)SMEM_DYN);
    cudaFuncSetAttribute(k_pre, cudaFuncAttributeMaxDynamicSharedMemorySize,
                         (int)PRE_SMEM);

    k_pre<<<N / IB, 128, PRE_SMEM>>>(embs, W, pcW, pcb, aW);      // launch 0
    k_big<<<dim3(N / BMJ, N / I_PER_CTA), 256, SMEM_DYN>>>(pde, adj, ab);  // launch 1
    k_out<<<N / RPB, 256>>>(embs, out);                           // launch 2
}